// round 8
// baseline (speedup 1.0000x reference)
#include <cuda_runtime.h>

// HSE (hard-sigmoid squeeze-excitation) for x[64, 768, 28, 28] fp32.
// R7: single persistent dataflow kernel. Pool stream and scale stream run
// concurrently, scale trailing pool by 2 rounds (~26 MB) so the x re-read
// hits L2. 64 dedicated MLP blocks bridge the two via per-batch flags.
// DRAM traffic drops 406 MB -> 308 MB and read/write overlap.

#define BATCH   64
#define CH      768
#define HID     192
#define HW      784
#define PLANES  (BATCH * CH)        // 49152
#define VEC4    (HW / 4)            // 196 float4 per plane

#define NBLK    592                 // <= 152 SMs * 4 resident (GB300)
#define NMLP    64
#define NWRK    (NBLK - NMLP)       // 528 worker blocks
#define WWARPS  (NWRK * 8)          // 4224 worker warps
#define NROUND  ((PLANES + WWARPS - 1) / WWARPS)   // 12
#define LAG     2                   // scale trails pool by 2 rounds

__device__ int            g_cnt[BATCH];
__device__ volatile int   g_ready[BATCH];
__device__ float          g_pooled[PLANES];
__device__ float          g_sc[PLANES];

__global__ void init_kernel() {
    int t = threadIdx.x;
    if (t < BATCH) { g_cnt[t] = CH; g_ready[t] = 0; }
}

__global__ __launch_bounds__(256, 4)
void fused_kernel(const float4* __restrict__ x,
                  const float4* __restrict__ w1,
                  const float*  __restrict__ b1,
                  const float2* __restrict__ w2,
                  const float*  __restrict__ b2,
                  float4*       __restrict__ out) {
    __shared__ __align__(16) float p_s[CH];
    __shared__ __align__(16) float h_s[HID];

    const int blk  = blockIdx.x;
    const int t    = threadIdx.x;
    const int lane = t & 31;
    const int wid  = t >> 5;

    if (blk < NMLP) {
        // ---------------- MLP block: one batch ----------------
        const int b = blk;
        if (t == 0) {
            while (*((volatile int*)&g_cnt[b]) != 0) __nanosleep(128);
        }
        __syncthreads();
        __threadfence();

        p_s[t]       = g_pooled[b * CH + t];
        p_s[t + 256] = g_pooled[b * CH + t + 256];
        p_s[t + 512] = g_pooled[b * CH + t + 512];
        __syncthreads();

        // phase 1: h = relu(w1 @ pooled + b1), warp per row (coalesced)
        const float4* pv = reinterpret_cast<const float4*>(p_s);
        for (int r = wid; r < HID; r += 8) {
            const float4* wrow = w1 + (size_t)r * (CH / 4);
            float acc = 0.0f;
#pragma unroll
            for (int i = 0; i < 6; i++) {
                float4 wv = wrow[lane + 32 * i];
                float4 p  = pv[lane + 32 * i];
                acc += wv.x * p.x + wv.y * p.y + wv.z * p.z + wv.w * p.w;
            }
#pragma unroll
            for (int off = 16; off; off >>= 1)
                acc += __shfl_xor_sync(0xffffffffu, acc, off);
            if (lane == 0) h_s[r] = fmaxf(acc + b1[r], 0.0f);
        }
        __syncthreads();

        // phase 2: s = hardsigmoid(w2 @ h + b2), warp per output (coalesced)
        const float2* hv = reinterpret_cast<const float2*>(h_s);
        for (int c = wid; c < CH; c += 8) {
            const float2* wrow = w2 + (size_t)c * (HID / 2);
            float acc = 0.0f;
#pragma unroll
            for (int i = 0; i < 3; i++) {
                float2 wv = wrow[lane + 32 * i];
                float2 h  = hv[lane + 32 * i];
                acc += wv.x * h.x + wv.y * h.y;
            }
#pragma unroll
            for (int off = 16; off; off >>= 1)
                acc += __shfl_xor_sync(0xffffffffu, acc, off);
            if (lane == 0)
                g_sc[b * CH + c] = __saturatef(fmaf(acc + b2[c], 1.0f / 6.0f, 0.5f));
        }
        __syncthreads();
        __threadfence();
        if (t == 0) g_ready[b] = 1;
        return;
    }

    // ---------------- worker block: pool + trailing scale ----------------
    const int gw = (blk - NMLP) * 8 + wid;   // 0..4223
    int lastReady = -1;

    for (int r = 0; r < NROUND + LAG; r++) {
        // pool plane for round r
        if (r < NROUND) {
            int p = gw + r * WWARPS;
            if (p < PLANES) {
                const float4* px = x + (size_t)p * VEC4;
                float s = 0.0f;
#pragma unroll
                for (int i = 0; i < 6; i++) {
                    float4 v = px[lane + 32 * i];
                    s += (v.x + v.y) + (v.z + v.w);
                }
                if (lane < 4) {
                    float4 v = px[192 + lane];
                    s += (v.x + v.y) + (v.z + v.w);
                }
#pragma unroll
                for (int off = 16; off; off >>= 1)
                    s += __shfl_xor_sync(0xffffffffu, s, off);
                if (lane == 0) {
                    g_pooled[p] = s * (1.0f / 784.0f);
                    __threadfence();
                    atomicSub(&g_cnt[p / CH], 1);
                }
            }
        }
        // scale plane pooled LAG rounds ago (L2-hot)
        int rs = r - LAG;
        if (rs >= 0) {
            int p = gw + rs * WWARPS;
            if (p < PLANES) {
                int b = p / CH;
                if (b > lastReady) {
                    while (g_ready[b] == 0) __nanosleep(64);
                    __threadfence();
                    lastReady = b;
                }
                float sv = g_sc[p];
                const float4* px = x   + (size_t)p * VEC4;
                float4*       po = out + (size_t)p * VEC4;
#pragma unroll
                for (int i = 0; i < 6; i++) {
                    float4 v = __ldcs(&px[lane + 32 * i]);
                    v.x *= sv; v.y *= sv; v.z *= sv; v.w *= sv;
                    __stcs(&po[lane + 32 * i], v);
                }
                if (lane < 4) {
                    float4 v = __ldcs(&px[192 + lane]);
                    v.x *= sv; v.y *= sv; v.z *= sv; v.w *= sv;
                    __stcs(&po[192 + lane], v);
                }
            }
        }
    }
}

// ---------------------------------------------------------------------------
extern "C" void kernel_launch(void* const* d_in, const int* in_sizes, int n_in,
                              void* d_out, int out_size) {
    const float4* x  = (const float4*)d_in[0];
    const float4* w1 = (const float4*)d_in[1];
    const float*  b1 = (const float*)d_in[2];
    const float2* w2 = (const float2*)d_in[3];
    const float*  b2 = (const float*)d_in[4];
    float4* out = (float4*)d_out;

    init_kernel<<<1, 64>>>();
    fused_kernel<<<NBLK, 256>>>(x, w1, b1, w2, b2, out);
}